// round 16
// baseline (speedup 1.0000x reference)
#include <cuda_runtime.h>
#include <cstdint>

#define B_SZ 16
#define D_DIM 128
#define T_SZ 4096
#define KCODES 1024
#define NVEC (B_SZ * T_SZ)
#define ROWS 128
#define NCTA (NVEC / ROWS)
#define NTHR 256
#define CAPR 8
#define MARGIN 2.5f
#define QSCALE 16.0f
#define QINV (1.0f / 256.0f)

#define OFF_Q 1
#define OFF_PERP (1 + B_SZ * D_DIM * T_SZ)
#define OFF_IDX (2 + B_SZ * D_DIM * T_SZ)

__device__ float g_cnorm[KCODES];
__device__ int g_cq[8 * 32 * 128];   // [chunk][k][code] packed s8x4
__device__ float g_counts[KCODES];
__device__ float g_loss;

// dynamic smem offsets (base 1024-aligned)
#define SO_XQ 0u        // 32 k x 136 ints (544B/row, 32B pad) = 17408
#define SO_CQ 17408u    // 2 x 16384 (code chunks, [k][code] ints)
#define SO_XF 50176u    // 128 x 129 fp32 = 66048
#define SO_CN 116224u   // 1024 fp32
#define SO_CAND 120320u // 256 thr x 8 rows x 8 u16 = 32768
#define SO_MS 153088u   // 128 x 16 fp32 = 8192
#define SO_MC 161280u   // 128 x 16 int = 8192
#define SO_BI 169472u   // 128 int
#define SO_RED 169984u  // 64
#define SMEM_DYN 171072u

__device__ __forceinline__ uint32_t smem_u32(const void* p) {
    uint32_t a;
    asm("{ .reg .u64 t; cvta.to.shared.u64 t, %1; cvt.u32.u64 %0, t; }" : "=r"(a) : "l"(p));
    return a;
}

__device__ __forceinline__ int q8(float v) {
    int q = __float2int_rn(v * QSCALE);
    return q < -127 ? -127 : (q > 127 ? 127 : q);
}

__device__ __forceinline__ void load_chunk(uint32_t sbCQ, int chunk, int buf) {
    const char* src0 = (const char*)g_cq + (size_t)chunk * 16384;
    uint32_t dst0 = sbCQ + ((uint32_t)buf << 14);
    for (int u = threadIdx.x; u < 1024; u += NTHR) {
        asm volatile("cp.async.cg.shared.global [%0], [%1], 16;"
                     :: "r"(dst0 + u * 16), "l"(__cvta_generic_to_global(src0 + u * 16))
                     : "memory");
    }
    asm volatile("cp.async.commit_group;" ::: "memory");
}

__global__ void vq_prep(const float* __restrict__ cb) {
    int k = blockIdx.x, t = threadIdx.x;
    __shared__ float vals[128];
    __shared__ float ws[4];
    float v = cb[k * D_DIM + t];
    vals[t] = v;
    float s = v * v;
#pragma unroll
    for (int o = 16; o; o >>= 1) s += __shfl_xor_sync(0xFFFFFFFFu, s, o);
    if ((t & 31) == 0) ws[t >> 5] = s;
    __syncthreads();
    if (t < 32) {
        int p = 0;
#pragma unroll
        for (int b = 0; b < 4; ++b)
            p |= (q8(vals[4 * t + b]) & 0xFF) << (8 * b);
        g_cq[(k >> 7) * 4096 + t * 128 + (k & 127)] = p;
    }
    if (t == 0) {
        g_cnorm[k] = 0.5f * (ws[0] + ws[1] + ws[2] + ws[3]);
        g_counts[k] = 0.0f;
        if (k == 0) g_loss = 0.0f;
    }
}

__global__ __launch_bounds__(NTHR, 1)
void vq_main(const float* __restrict__ in, const float* __restrict__ cb,
             float* __restrict__ out) {
    extern __shared__ char smraw[];
    const int tid = threadIdx.x;
    uint32_t sb_raw = smem_u32(smraw);
    uint32_t sb = (sb_raw + 1023u) & ~1023u;
    char* sm = smraw + (sb - sb_raw);

    float* xf = (float*)(sm + SO_XF);
    float* cn = (float*)(sm + SO_CN);
    unsigned short* cand = (unsigned short*)(sm + SO_CAND);
    float* mS = (float*)(sm + SO_MS);
    int* mC = (int*)(sm + SO_MC);
    int* bi_s = (int*)(sm + SO_BI);
    float* red = (float*)(sm + SO_RED);

    const int bIdx = blockIdx.x >> 5;
    const int t0 = (blockIdx.x & 31) << 7;
    const float* inb = in + (size_t)bIdx * (D_DIM * T_SZ) + t0;

    const int tr = tid & 15, tc = tid >> 4;   // rows 8tr.., codes 8tc.. per chunk

    for (int i = tid; i < KCODES; i += NTHR) cn[i] = g_cnorm[i];

    // x tile fp32 (padded) — coalesced over time index j
    for (int i = tid; i < ROWS * D_DIM; i += NTHR) {
        int d = i >> 7, j = i & 127;
        xf[j * 129 + d] = inb[(size_t)d * T_SZ + j];
    }
    load_chunk(sb + SO_CQ, 0, 0);
    __syncthreads();

    // pack x k-major s8x4: xq[k][row]
    for (int i = tid; i < ROWS * 32; i += NTHR) {
        int row = i & 127, kk = i >> 7;
        const float* xp = &xf[row * 129 + 4 * kk];
        int p = (q8(xp[0]) & 0xFF) | ((q8(xp[1]) & 0xFF) << 8) |
                ((q8(xp[2]) & 0xFF) << 16) | ((q8(xp[3]) & 0xFF) << 24);
        *(int*)(sm + SO_XQ + (uint32_t)kk * 544u + (uint32_t)row * 4u) = p;
    }
    __syncthreads();

    unsigned short* candp = cand + tid * 64;  // [8 rows][8 ring]
    float bestR[8];
    int cnts[8];
#pragma unroll
    for (int i = 0; i < 8; ++i) { bestR[i] = -3.0e38f; cnts[i] = 0; }

    const uint32_t xoff = (uint32_t)(32 * tr);
    const uint32_t coff = (uint32_t)(32 * tc);

    for (int c = 0; c < 8; ++c) {
        if (c < 7) {
            load_chunk(sb + SO_CQ, c + 1, (c + 1) & 1);
            asm volatile("cp.async.wait_group 1;" ::: "memory");
        } else {
            asm volatile("cp.async.wait_group 0;" ::: "memory");
        }
        __syncthreads();
        const char* cqb = sm + SO_CQ + ((uint32_t)(c & 1) << 14);

        int acc[8][8];
#pragma unroll
        for (int i = 0; i < 8; ++i)
#pragma unroll
            for (int j = 0; j < 8; ++j) acc[i][j] = 0;

#pragma unroll 4
        for (int k = 0; k < 32; ++k) {
            int4 xa = *(const int4*)(sm + SO_XQ + (uint32_t)k * 544u + xoff);
            int4 xb = *(const int4*)(sm + SO_XQ + (uint32_t)k * 544u + xoff + 16u);
            int4 ca = *(const int4*)(cqb + (uint32_t)k * 512u + coff);
            int4 cb4 = *(const int4*)(cqb + (uint32_t)k * 512u + coff + 16u);
            int xv[8] = {xa.x, xa.y, xa.z, xa.w, xb.x, xb.y, xb.z, xb.w};
            int cv[8] = {ca.x, ca.y, ca.z, ca.w, cb4.x, cb4.y, cb4.z, cb4.w};
#pragma unroll
            for (int i = 0; i < 8; ++i)
#pragma unroll
                for (int j = 0; j < 8; ++j)
                    acc[i][j] = __dp4a(xv[i], cv[j], acc[i][j]);
        }

        int gc0 = (c << 7) + (tc << 3);
#pragma unroll
        for (int j = 0; j < 8; ++j) {
            float cnj = cn[gc0 + j];
#pragma unroll
            for (int i = 0; i < 8; ++i) {
                float s = (float)acc[i][j] * QINV - cnj;
                if (s > bestR[i] - MARGIN) {
                    candp[i * 8 + (cnts[i] & (CAPR - 1))] = (unsigned short)(gc0 + j);
                    ++cnts[i];
                    bestR[i] = fmaxf(bestR[i], s);
                }
            }
        }
        __syncthreads();
    }

    // exact fp32 rescore per thread-row, then write per-(row,tc) partials
#pragma unroll 1
    for (int i = 0; i < 8; ++i) {
        int row = 8 * tr + i;
        const float* xr = xf + row * 129;
        float sB = -3.4e38f;
        int cB = KCODES;
        int n = cnts[i] < CAPR ? cnts[i] : CAPR;
        for (int j = 0; j < n; ++j) {
            int code = candp[i * 8 + j];
            const float4* q = (const float4*)(cb + (code << 7));
            float a0 = 0.f, a1 = 0.f, a2 = 0.f, a3 = 0.f;
#pragma unroll
            for (int d = 0; d < 32; ++d) {
                float4 v = __ldg(q + d);
                a0 = fmaf(v.x, xr[4 * d + 0], a0);
                a1 = fmaf(v.y, xr[4 * d + 1], a1);
                a2 = fmaf(v.z, xr[4 * d + 2], a2);
                a3 = fmaf(v.w, xr[4 * d + 3], a3);
            }
            float s = (a0 + a1) + (a2 + a3) - cn[code];
            if (s > sB || (s == sB && code < cB)) { sB = s; cB = code; }
        }
        mS[row * 16 + tc] = sB;
        mC[row * 16 + tc] = cB;
    }
    __syncthreads();

    if (tid < 128) {
        float sB = mS[tid * 16];
        int cB = mC[tid * 16];
#pragma unroll 1
        for (int g = 1; g < 16; ++g) {
            float s = mS[tid * 16 + g];
            int cc = mC[tid * 16 + g];
            if (s > sB || (s == sB && cc < cB)) { sB = s; cB = cc; }
        }
        bi_s[tid] = cB;
        out[OFF_IDX + (size_t)bIdx * T_SZ + t0 + tid] = (float)cB;
        atomicAdd(&g_counts[cB], 1.0f);
    }
    __syncthreads();

    // gather selected codes into xf (overwrite x), accumulate loss
    float lpart = 0.f;
    for (int i = tid; i < ROWS * 32; i += NTHR) {
        int rw = i >> 5, c4 = i & 31;
        int code = bi_s[rw];
        float4 q = __ldg((const float4*)(cb + (code << 7)) + c4);
        float* xp = &xf[rw * 129 + (c4 << 2)];
        float d0 = q.x - xp[0], d1 = q.y - xp[1], d2 = q.z - xp[2], d3 = q.w - xp[3];
        lpart += d0 * d0 + d1 * d1 + d2 * d2 + d3 * d3;
        xp[0] = q.x; xp[1] = q.y; xp[2] = q.z; xp[3] = q.w;
    }
#pragma unroll
    for (int o = 16; o; o >>= 1) lpart += __shfl_xor_sync(0xFFFFFFFFu, lpart, o);
    if ((tid & 31) == 0) red[tid >> 5] = lpart;
    __syncthreads();
    if (tid == 0) {
        float s = 0.f;
        for (int q = 0; q < 8; ++q) s += red[q];
        atomicAdd(&g_loss, s);
    }

    // transposed coalesced quantized write
    for (int i = tid; i < ROWS * D_DIM; i += NTHR) {
        int d = i >> 7, j = i & 127;
        out[OFF_Q + (size_t)bIdx * (D_DIM * T_SZ) + (size_t)d * T_SZ + t0 + j] =
            xf[j * 129 + d];
    }
}

__global__ void vq_fin(float* __restrict__ out) {
    __shared__ float sh[256];
    int t = threadIdx.x;
    float h = 0.f;
    for (int k = t; k < KCODES; k += 256) {
        float p = g_counts[k] * (1.0f / (float)NVEC);
        h += p * logf(p + 1e-10f);
    }
    sh[t] = h;
    __syncthreads();
    for (int o = 128; o; o >>= 1) {
        if (t < o) sh[t] += sh[t + o];
        __syncthreads();
    }
    if (t == 0) {
        out[0] = 0.25f * g_loss / (float)(B_SZ * D_DIM * T_SZ);
        out[OFF_PERP] = expf(-sh[0]);
    }
}

extern "C" void kernel_launch(void* const* d_in, const int* in_sizes, int n_in,
                              void* d_out, int out_size) {
    const float* in = (const float*)d_in[0];
    const float* cb = (const float*)d_in[1];
    if (n_in >= 2 && in_sizes[0] == KCODES * D_DIM) {
        const float* t = in; in = cb; cb = t;
    }
    float* out = (float*)d_out;
    cudaFuncSetAttribute(vq_main, cudaFuncAttributeMaxDynamicSharedMemorySize, SMEM_DYN);
    vq_prep<<<KCODES, 128>>>(cb);
    vq_main<<<NCTA, NTHR, SMEM_DYN>>>(in, cb, out);
    vq_fin<<<1, 256>>>(out);
}